// round 12
// baseline (speedup 1.0000x reference)
#include <cuda_runtime.h>
#include <cuda_bf16.h>
#include <math.h>

#define NHQ   16
#define NKV   8
#define HD    128
#define HID   1024
#define SEQ   2048
#define BATCH 2
#define ROWS  (BATCH*SEQ)   // 4096
#define NQKV  4096
#define EPSV  1e-6f

typedef __nv_bfloat16 bf16;

#define QSCALE 0.12753123810100868f
#define SMAX 18.0f

// ---------------- static scratch ----------------
__device__ __align__(256) float g_qkvraw[(size_t)ROWS * NQKV];

__device__ __align__(256) bf16 g_xhi[(size_t)ROWS * HID];
__device__ __align__(256) bf16 g_xlo[(size_t)ROWS * HID];
__device__ __align__(256) bf16 g_wqkvhi[(size_t)HID * NQKV];
__device__ __align__(256) bf16 g_wqkvlo[(size_t)HID * NQKV];
__device__ __align__(256) bf16 g_wohi[(size_t)NHQ * HD * HID];
__device__ __align__(256) bf16 g_wolo[(size_t)NHQ * HD * HID];

__device__ __align__(256) bf16 g_qhi[(size_t)BATCH * NHQ * SEQ * HD];
__device__ __align__(256) bf16 g_qlo[(size_t)BATCH * NHQ * SEQ * HD];
__device__ __align__(256) bf16 g_khi[(size_t)BATCH * NKV * SEQ * HD];
__device__ __align__(256) bf16 g_klo[(size_t)BATCH * NKV * SEQ * HD];
__device__ __align__(256) bf16 g_vhi[(size_t)BATCH * NKV * SEQ * HD];
__device__ __align__(256) bf16 g_vlo[(size_t)BATCH * NKV * SEQ * HD];

__device__ __align__(256) bf16 g_chi[(size_t)ROWS * NHQ * HD];
__device__ __align__(256) bf16 g_clo[(size_t)ROWS * NHQ * HD];

// ---------------- PTX helpers ----------------
__device__ __forceinline__ unsigned su32(const void* p) {
    return (unsigned)__cvta_generic_to_shared(p);
}
__device__ __forceinline__ void cp16(unsigned d, const void* s) {
    asm volatile("cp.async.ca.shared.global [%0],[%1],16;\n" :: "r"(d), "l"(s));
}
__device__ __forceinline__ void cpcommit() { asm volatile("cp.async.commit_group;\n"); }
#define CP_WAIT1() asm volatile("cp.async.wait_group 1;\n")
#define CP_WAIT0() asm volatile("cp.async.wait_group 0;\n")

__device__ __forceinline__ void ldmx4(unsigned a, unsigned& r0, unsigned& r1,
                                      unsigned& r2, unsigned& r3) {
    asm volatile("ldmatrix.sync.aligned.m8n8.x4.shared.b16 {%0,%1,%2,%3},[%4];\n"
                 : "=r"(r0), "=r"(r1), "=r"(r2), "=r"(r3) : "r"(a));
}
__device__ __forceinline__ void ldmx4t(unsigned a, unsigned& r0, unsigned& r1,
                                       unsigned& r2, unsigned& r3) {
    asm volatile("ldmatrix.sync.aligned.m8n8.x4.trans.shared.b16 {%0,%1,%2,%3},[%4];\n"
                 : "=r"(r0), "=r"(r1), "=r"(r2), "=r"(r3) : "r"(a));
}
__device__ __forceinline__ void stmx4(unsigned a, unsigned r0, unsigned r1,
                                      unsigned r2, unsigned r3) {
    asm volatile("stmatrix.sync.aligned.m8n8.x4.shared.b16 [%0],{%1,%2,%3,%4};\n"
                 :: "r"(a), "r"(r0), "r"(r1), "r"(r2), "r"(r3) : "memory");
}
__device__ __forceinline__ void mma16816(float* d, const unsigned* a, const unsigned* b) {
    asm volatile(
        "mma.sync.aligned.m16n8k16.row.col.f32.bf16.bf16.f32 "
        "{%0,%1,%2,%3},{%4,%5,%6,%7},{%8,%9},{%0,%1,%2,%3};\n"
        : "+f"(d[0]), "+f"(d[1]), "+f"(d[2]), "+f"(d[3])
        : "r"(a[0]), "r"(a[1]), "r"(a[2]), "r"(a[3]), "r"(b[0]), "r"(b[1]));
}
__device__ __forceinline__ float ex2(float x) {
    float r;
    asm("ex2.approx.ftz.f32 %0, %1;" : "=f"(r) : "f"(x));
    return r;
}
__device__ __forceinline__ void split2(float x, float y, unsigned& hi, unsigned& lo) {
    __nv_bfloat162 h = __floats2bfloat162_rn(x, y);
    float2 hf = __bfloat1622float2(h);
    __nv_bfloat162 l = __floats2bfloat162_rn(x - hf.x, y - hf.y);
    hi = *(unsigned*)&h;
    lo = *(unsigned*)&l;
}

// swizzled smem offsets (bytes)
__device__ __forceinline__ int offA64(int r, int k) {
    return r * 64 + ((((k >> 3) ^ ((r >> 1) & 3))) << 4) + ((k & 7) << 1);
}
__device__ __forceinline__ int off128(int r, int k) {
    return r * 128 + ((((k >> 3) ^ (r & 7))) << 4) + ((k & 7) << 1);
}
__device__ __forceinline__ int off256(int r, int n) {
    return r * 256 + ((((n >> 3) ^ (r & 7))) << 4) + ((n & 7) << 1);
}

// ---------------- elementwise fp32 -> bf16 hi/lo split ----------------
__global__ __launch_bounds__(256) void split_kernel(
    const float* __restrict__ x, bf16* __restrict__ hi, bf16* __restrict__ lo, int n)
{
    for (int i = blockIdx.x * 256 + threadIdx.x; i < n; i += gridDim.x * 256) {
        float v = x[i];
        bf16 h = __float2bfloat16(v);
        hi[i] = h;
        lo[i] = __float2bfloat16(v - __bfloat162float(h));
    }
}

// ---------------- concat Wq|Wk|Wv + split ----------------
__global__ __launch_bounds__(256) void splitcat_qkv(
    const float* __restrict__ Wq, const float* __restrict__ Wk,
    const float* __restrict__ Wv,
    bf16* __restrict__ hi, bf16* __restrict__ lo)
{
    int total = HID * NQKV;
    for (int i = blockIdx.x * 256 + threadIdx.x; i < total; i += gridDim.x * 256) {
        int k = i >> 12;
        int n = i & 4095;
        float v;
        if (n < 2048)      v = Wq[(size_t)k * 2048 + n];
        else if (n < 3072) v = Wk[(size_t)k * 1024 + (n - 2048)];
        else               v = Wv[(size_t)k * 1024 + (n - 3072)];
        bf16 h = __float2bfloat16(v);
        hi[i] = h;
        lo[i] = __float2bfloat16(v - __bfloat162float(h));
    }
}

// ================= double-buffered bf16-split GEMM (NN) — unchanged =================
constexpr int GBM = 128, GBN = 128, GBK = 32;

__global__ __launch_bounds__(256) void gemm_split(
    const bf16* __restrict__ Ahi, const bf16* __restrict__ Alo,
    const bf16* __restrict__ Bhi, const bf16* __restrict__ Blo,
    float* __restrict__ C, int M, int N, int K)
{
    extern __shared__ char sm[];
    int tid = threadIdx.x, lane = tid & 31, warp = tid >> 5;
    int bx = blockIdx.x, by = blockIdx.y;
    int wm = warp >> 2, wn = warp & 3;

    float acc[4][4][4];
    #pragma unroll
    for (int a = 0; a < 4; a++)
        #pragma unroll
        for (int b = 0; b < 4; b++)
            #pragma unroll
            for (int c = 0; c < 4; c++) acc[a][b][c] = 0.f;

    int nIter = K / GBK;

    int ar = tid >> 2, ag = (tid & 3) << 3;
    int bkr = tid >> 4, bg = (tid & 15) << 3;

    auto issue = [&](int st, int k0) {
        char* base = sm + st * 32768;
        #pragma unroll
        for (int p = 0; p < 2; p++) {
            int r = ar + p * 64;
            int so = offA64(r, ag);
            size_t go = (size_t)(by * GBM + r) * K + k0 + ag;
            cp16(su32(base + so), Ahi + go);
            cp16(su32(base + 8192 + so), Alo + go);
        }
        #pragma unroll
        for (int p = 0; p < 2; p++) {
            int kr = bkr + p * 16;
            int so = off256(kr, bg);
            size_t go = (size_t)(k0 + kr) * N + bx * GBN + bg;
            cp16(su32(base + 16384 + so), Bhi + go);
            cp16(su32(base + 24576 + so), Blo + go);
        }
    };

    issue(0, 0);
    cpcommit();

    int arow = (lane & 7) + ((lane >> 3) & 1) * 8;
    int aksel = (lane >> 4) * 8;
    int tk = (lane & 7) + ((lane >> 3) & 1) * 8;
    int tn = (lane >> 4) * 8;

    for (int it = 0; it < nIter; ++it) {
        if (it + 1 < nIter) {
            issue((it + 1) & 1, (it + 1) * GBK);
            cpcommit();
            CP_WAIT1();
        } else {
            CP_WAIT0();
        }
        __syncthreads();
        char* base = sm + (it & 1) * 32768;

        #pragma unroll
        for (int ks = 0; ks < GBK; ks += 16) {
            unsigned ah[4][4], al[4][4], bh[4][2], bl[4][2];
            #pragma unroll
            for (int mt = 0; mt < 4; mt++) {
                int so = offA64(wm * 64 + mt * 16 + arow, ks + aksel);
                ldmx4(su32(base + so), ah[mt][0], ah[mt][1], ah[mt][2], ah[mt][3]);
                ldmx4(su32(base + 8192 + so), al[mt][0], al[mt][1], al[mt][2], al[mt][3]);
            }
            #pragma unroll
            for (int ng = 0; ng < 2; ng++) {
                int so = off256(ks + tk, wn * 32 + ng * 16 + tn);
                unsigned r0, r1, r2, r3;
                ldmx4t(su32(base + 16384 + so), r0, r1, r2, r3);
                bh[2 * ng][0] = r0; bh[2 * ng][1] = r1;
                bh[2 * ng + 1][0] = r2; bh[2 * ng + 1][1] = r3;
                ldmx4t(su32(base + 24576 + so), r0, r1, r2, r3);
                bl[2 * ng][0] = r0; bl[2 * ng][1] = r1;
                bl[2 * ng + 1][0] = r2; bl[2 * ng + 1][1] = r3;
            }
            #pragma unroll
            for (int mt = 0; mt < 4; mt++)
                #pragma unroll
                for (int nf = 0; nf < 4; nf++) {
                    mma16816(acc[mt][nf], ah[mt], bh[nf]);
                    mma16816(acc[mt][nf], ah[mt], bl[nf]);
                    mma16816(acc[mt][nf], al[mt], bh[nf]);
                }
        }
        __syncthreads();
    }

    #pragma unroll
    for (int mt = 0; mt < 4; mt++)
        #pragma unroll
        for (int nf = 0; nf < 4; nf++) {
            int r = by * GBM + wm * 64 + mt * 16 + (lane >> 2);
            int c = bx * GBN + wn * 32 + nf * 8 + (lane & 3) * 2;
            *(float2*)(C + (size_t)r * N + c) = make_float2(acc[mt][nf][0], acc[mt][nf][1]);
            *(float2*)(C + (size_t)(r + 8) * N + c) = make_float2(acc[mt][nf][2], acc[mt][nf][3]);
        }
}

// ================= flash attention: 512 thr, 16 warps = 8m x 2c, P via smem =================
// smem layout (bytes):
//   Qhi 0 (32K), Qlo 32768 (32K)
//   KV stage s at 65536 + s*65536: Khi +0, Klo +16384, Vhi +32768, Vlo +49152
//   Phi 196608 (16K), Plo 212992 (16K)
//   lbuf 229376: float[2][8][16] (1K)   -> total 230400
#define SM_KV   65536
#define SM_P    196608
#define SM_L    229376

__global__ __launch_bounds__(512) void flash_kernel(
    const bf16* __restrict__ qhi, const bf16* __restrict__ qlo,
    const bf16* __restrict__ khi, const bf16* __restrict__ klo,
    const bf16* __restrict__ vhi, const bf16* __restrict__ vlo,
    bf16* __restrict__ chi, bf16* __restrict__ clo)
{
    extern __shared__ char sm[];
    int tid = threadIdx.x, lane = tid & 31, wid = tid >> 5;
    int wm = wid >> 1, wc = wid & 1;       // m-group 0..7, column-half 0/1
    int qt = (gridDim.x - 1) - blockIdx.x;
    int bh = blockIdx.y;
    int b = bh >> 4, h = bh & 15, kvh = h >> 1;

    size_t qbase = ((size_t)(b * NHQ + h) * SEQ + (size_t)qt * 128) * HD;
    size_t kvbase = (size_t)(b * NKV + kvh) * SEQ * HD;

    // load Q (hi+lo): 128 x 128
    #pragma unroll
    for (int p = 0; p < 4; p++) {
        int idx = tid + p * 512;
        int r = idx >> 4, g = (idx & 15) << 3;
        int so = off256(r, g);
        size_t go = qbase + (size_t)r * HD + g;
        cp16(su32(sm + so), qhi + go);
        cp16(su32(sm + 32768 + so), qlo + go);
    }
    cpcommit();

    auto issueKV = [&](int st, int kt) {
        char* base = sm + SM_KV + st * 65536;
        size_t kb = kvbase + (size_t)kt * 64 * HD;
        #pragma unroll
        for (int p = 0; p < 2; p++) {
            int idx = tid + p * 512;
            int r = idx >> 4, g = (idx & 15) << 3;
            int so = off256(r, g);
            size_t go = kb + (size_t)r * HD + g;
            cp16(su32(base + so), khi + go);
            cp16(su32(base + 16384 + so), klo + go);
            cp16(su32(base + 32768 + so), vhi + go);
            cp16(su32(base + 49152 + so), vlo + go);
        }
    };

    int nT = 2 * qt + 2;
    issueKV(0, 0);
    cpcommit();

    float oacc[8][4];        // 16 rows x 64 hd cols (this warp's half)
    #pragma unroll
    for (int f = 0; f < 8; f++)
        #pragma unroll
        for (int c = 0; c < 4; c++) oacc[f][c] = 0.f;
    float l0 = 0.f, l1 = 0.f;

    int arow = (lane & 7) + ((lane >> 3) & 1) * 8;
    int aksel = (lane >> 4) * 8;
    int bn = (lane & 7) + (lane >> 4) * 8;
    int bk = ((lane >> 3) & 1) * 8;
    int tk = (lane & 7) + ((lane >> 3) & 1) * 8;
    int tn = (lane >> 4) * 8;
    int r0g = qt * 128 + wm * 16 + (lane >> 2);

    for (int kt = 0; kt < nT; ++kt) {
        if (kt + 1 < nT) {
            issueKV((kt + 1) & 1, kt + 1);
            cpcommit();
            CP_WAIT1();
        } else {
            CP_WAIT0();
        }
        __syncthreads();
        char* kbase = sm + SM_KV + (kt & 1) * 65536;
        char* vbase = kbase + 32768;

        // ---- S = Q*K^T: 16 rows x 32 cols (this warp's half), init = -SMAX ----
        float sacc[4][4];
        #pragma unroll
        for (int f = 0; f < 4; f++)
            #pragma unroll
            for (int c = 0; c < 4; c++) sacc[f][c] = -SMAX;

        #pragma unroll
        for (int ks = 0; ks < HD; ks += 16) {
            unsigned qh[4], ql[4];
            int qo = off256(wm * 16 + arow, ks + aksel);
            ldmx4(su32(sm + qo), qh[0], qh[1], qh[2], qh[3]);
            ldmx4(su32(sm + 32768 + qo), ql[0], ql[1], ql[2], ql[3]);
            #pragma unroll
            for (int ng = 0; ng < 2; ng++) {
                int ncol = wc * 32 + ng * 16;
                int so = off256(ncol + bn, ks + bk);
                unsigned r0, r1, r2, r3;
                unsigned kh0[2], kh1[2], kl0[2], kl1[2];
                ldmx4(su32(kbase + so), r0, r1, r2, r3);
                kh0[0] = r0; kh0[1] = r1; kh1[0] = r2; kh1[1] = r3;
                ldmx4(su32(kbase + 16384 + so), r0, r1, r2, r3);
                kl0[0] = r0; kl0[1] = r1; kl1[0] = r2; kl1[1] = r3;
                mma16816(sacc[2 * ng], qh, kh0);
                mma16816(sacc[2 * ng], qh, kl0);
                mma16816(sacc[2 * ng], ql, kh0);
                mma16816(sacc[2 * ng + 1], qh, kh1);
                mma16816(sacc[2 * ng + 1], qh, kl1);
                mma16816(sacc[2 * ng + 1], ql, kh1);
            }
        }

        // ---- causal mask ----
        if (kt >= 2 * qt) {
            #pragma unroll
            for (int nf = 0; nf < 4; nf++) {
                int col = kt * 64 + wc * 32 + nf * 8 + (lane & 3) * 2;
                if (col > r0g)     sacc[nf][0] = -10000.f;
                if (col + 1 > r0g) sacc[nf][1] = -10000.f;
                if (col > r0g + 8)     sacc[nf][2] = -10000.f;
                if (col + 1 > r0g + 8) sacc[nf][3] = -10000.f;
            }
        }

        // ---- static-max softmax ----
        float ps0 = 0.f, ps1 = 0.f;
        #pragma unroll
        for (int nf = 0; nf < 4; nf++) {
            sacc[nf][0] = ex2(sacc[nf][0]);
            sacc[nf][1] = ex2(sacc[nf][1]);
            sacc[nf][2] = ex2(sacc[nf][2]);
            sacc[nf][3] = ex2(sacc[nf][3]);
            ps0 += sacc[nf][0] + sacc[nf][1];
            ps1 += sacc[nf][2] + sacc[nf][3];
        }
        l0 += ps0;
        l1 += ps1;

        // ---- P -> bf16 hi/lo A-fragments, store to smem via stmatrix ----
        #pragma unroll
        for (int j = 0; j < 2; j++) {
            unsigned ph[4], pl[4];
            split2(sacc[2 * j][0], sacc[2 * j][1], ph[0], pl[0]);
            split2(sacc[2 * j][2], sacc[2 * j][3], ph[1], pl[1]);
            split2(sacc[2 * j + 1][0], sacc[2 * j + 1][1], ph[2], pl[2]);
            split2(sacc[2 * j + 1][2], sacc[2 * j + 1][3], ph[3], pl[3]);
            int po = off128(wm * 16 + arow, wc * 32 + j * 16 + aksel);
            stmx4(su32(sm + SM_P + po), ph[0], ph[1], ph[2], ph[3]);
            stmx4(su32(sm + SM_P + 16384 + po), pl[0], pl[1], pl[2], pl[3]);
        }
        __syncthreads();   // P visible to partner warp

        // ---- O += P*V: 16 rows x 64 hd cols, k = full 64 kv ----
        #pragma unroll
        for (int j = 0; j < 4; j++) {
            unsigned pah[4], pal[4];
            int po = off128(wm * 16 + arow, j * 16 + aksel);
            ldmx4(su32(sm + SM_P + po), pah[0], pah[1], pah[2], pah[3]);
            ldmx4(su32(sm + SM_P + 16384 + po), pal[0], pal[1], pal[2], pal[3]);
            #pragma unroll
            for (int ng2 = 0; ng2 < 4; ng2++) {
                int so = off256(j * 16 + tk, wc * 64 + ng2 * 16 + tn);
                unsigned r0, r1, r2, r3, s0, s1, s2, s3;
                ldmx4t(su32(vbase + so), r0, r1, r2, r3);
                ldmx4t(su32(vbase + 16384 + so), s0, s1, s2, s3);
                unsigned vh0[2] = {r0, r1}, vh1[2] = {r2, r3};
                unsigned vl0[2] = {s0, s1}, vl1[2] = {s2, s3};
                mma16816(oacc[2 * ng2], pah, vh0);
                mma16816(oacc[2 * ng2], pal, vh0);
                mma16816(oacc[2 * ng2], pah, vl0);
                mma16816(oacc[2 * ng2 + 1], pah, vh1);
                mma16816(oacc[2 * ng2 + 1], pal, vh1);
                mma16816(oacc[2 * ng2 + 1], pah, vl1);
            }
        }
        __syncthreads();   // V stage + P buffer safe to reuse
    }

    // ---- combine l across column-halves, finalize ----
    l0 += __shfl_xor_sync(0xffffffffu, l0, 1);
    l0 += __shfl_xor_sync(0xffffffffu, l0, 2);
    l1 += __shfl_xor_sync(0xffffffffu, l1, 1);
    l1 += __shfl_xor_sync(0xffffffffu, l1, 2);
    float* lbuf = (float*)(sm + SM_L);   // [2][8][16]
    if ((lane & 3) == 0) {
        lbuf[(wc * 8 + wm) * 16 + (lane >> 2)] = l0;
        lbuf[(wc * 8 + wm) * 16 + 8 + (lane >> 2)] = l1;
    }
    __syncthreads();
    float lt0 = lbuf[(0 * 8 + wm) * 16 + (lane >> 2)] + lbuf[(1 * 8 + wm) * 16 + (lane >> 2)];
    float lt1 = lbuf[(0 * 8 + wm) * 16 + 8 + (lane >> 2)] + lbuf[(1 * 8 + wm) * 16 + 8 + (lane >> 2)];
    float i0 = 1.f / lt0, i1 = 1.f / lt1;

    size_t row0 = (size_t)b * SEQ + qt * 128 + wm * 16 + (lane >> 2);
    #pragma unroll
    for (int nf = 0; nf < 8; nf++) {
        int col = h * HD + wc * 64 + nf * 8 + (lane & 3) * 2;
        unsigned hi, lo;
        split2(oacc[nf][0] * i0, oacc[nf][1] * i0, hi, lo);
        *(unsigned*)(chi + row0 * (NHQ * HD) + col) = hi;
        *(unsigned*)(clo + row0 * (NHQ * HD) + col) = lo;
        split2(oacc[nf][2] * i1, oacc[nf][3] * i1, hi, lo);
        *(unsigned*)(chi + (row0 + 8) * (NHQ * HD) + col) = hi;
        *(unsigned*)(clo + (row0 + 8) * (NHQ * HD) + col) = lo;
    }
}

// ---------------- RMSNorm + RoPE + split (reads merged qkvraw) ----------------
__device__ __forceinline__ float blockSum128(float v) {
    #pragma unroll
    for (int o = 16; o > 0; o >>= 1) v += __shfl_xor_sync(0xffffffffu, v, o);
    __shared__ float s[4];
    if ((threadIdx.x & 31) == 0) s[threadIdx.x >> 5] = v;
    __syncthreads();
    float r = s[0] + s[1] + s[2] + s[3];
    __syncthreads();
    return r;
}

__global__ __launch_bounds__(HD) void normrope_kernel(
    const float* __restrict__ qkvraw,
    const float* __restrict__ qw, const float* __restrict__ kw,
    const int* __restrict__ pos,
    bf16* __restrict__ qhi, bf16* __restrict__ qlo,
    bf16* __restrict__ khi, bf16* __restrict__ klo,
    bf16* __restrict__ vhi, bf16* __restrict__ vlo)
{
    int row = blockIdx.y;
    int hh  = blockIdx.x;
    int t   = threadIdx.x;
    int b   = row / SEQ, s = row - b * SEQ;

    if (hh >= NHQ + NKV) {
        int kvh = hh - NHQ - NKV;
        float x = qkvraw[(size_t)row * NQKV + 3072 + kvh * HD + t];
        size_t o = (((size_t)(b * NKV + kvh)) * SEQ + s) * HD + t;
        bf16 hv = __float2bfloat16(x);
        vhi[o] = hv;
        vlo[o] = __float2bfloat16(x - __bfloat162float(hv));
        return;
    }

    float x; const float* w;
    bf16 *dhi, *dlo;
    bool isq = (hh < NHQ);
    if (isq) {
        x = qkvraw[(size_t)row * NQKV + hh * HD + t];
        w = qw;
        size_t o = (((size_t)(b * NHQ + hh)) * SEQ + s) * HD + t;
        dhi = qhi + o; dlo = qlo + o;
    } else {
        int kvh = hh - NHQ;
        x = qkvraw[(size_t)row * NQKV + 2048 + kvh * HD + t];
        w = kw;
        size_t o = (((size_t)(b * NKV + kvh)) * SEQ + s) * HD + t;
        dhi = khi + o; dlo = klo + o;
    }

    float ms = blockSum128(x * x) * (1.0f / HD);
    float nv = w[t] * (x * rsqrtf(ms + EPSV));

    __shared__ float sh[HD];
    sh[t] = nv;
    __syncthreads();

    int j = t & 63;
    double invf = exp(-(2.0 * j / (double)HD) * log(1.0e6));
    double ang  = (double)pos[s] * invf;
    float c  = (float)cos(ang);
    float sn = (float)sin(ang);
    float partner = (t < 64) ? -sh[t + 64] : sh[t - 64];
    float val = nv * c + partner * sn;
    if (isq) val *= QSCALE;

    bf16 hv = __float2bfloat16(val);
    *dhi = hv;
    *dlo = __float2bfloat16(val - __bfloat162float(hv));
}

// ---------------- launch ----------------
template <typename T>
static T* symaddr(const void* sym) {
    void* p = nullptr;
    cudaGetSymbolAddress(&p, sym);
    return (T*)p;
}

extern "C" void kernel_launch(void* const* d_in, const int* in_sizes, int n_in,
                              void* d_out, int out_size)
{
    const float* X   = (const float*)d_in[0];
    const int*   pos = (const int*)d_in[1];
    const float* Wq  = (const float*)d_in[2];
    const float* Wk  = (const float*)d_in[3];
    const float* Wv  = (const float*)d_in[4];
    const float* Wo  = (const float*)d_in[5];
    const float* qw  = (const float*)d_in[6];
    const float* kw  = (const float*)d_in[7];
    float* out = (float*)d_out;

    float* qkvraw = symaddr<float>(g_qkvraw);
    bf16* xhi = symaddr<bf16>(g_xhi);       bf16* xlo = symaddr<bf16>(g_xlo);
    bf16* wqkvhi = symaddr<bf16>(g_wqkvhi); bf16* wqkvlo = symaddr<bf16>(g_wqkvlo);
    bf16* wohi = symaddr<bf16>(g_wohi);     bf16* wolo = symaddr<bf16>(g_wolo);
    bf16* qhi = symaddr<bf16>(g_qhi);       bf16* qlo = symaddr<bf16>(g_qlo);
    bf16* khi = symaddr<bf16>(g_khi);       bf16* klo = symaddr<bf16>(g_klo);
    bf16* vhi = symaddr<bf16>(g_vhi);       bf16* vlo = symaddr<bf16>(g_vlo);
    bf16* chi = symaddr<bf16>(g_chi);       bf16* clo = symaddr<bf16>(g_clo);

    static int attr_done = 0;
    if (!attr_done) {
        cudaFuncSetAttribute(gemm_split, cudaFuncAttributeMaxDynamicSharedMemorySize, 65536);
        cudaFuncSetAttribute(flash_kernel, cudaFuncAttributeMaxDynamicSharedMemorySize, 230400);
        attr_done = 1;
    }

    // 0-2) splits
    split_kernel<<<1024, 256>>>(X, xhi, xlo, ROWS * HID);
    splitcat_qkv<<<1024, 256>>>(Wq, Wk, Wv, wqkvhi, wqkvlo);
    split_kernel<<<1024, 256>>>(Wo, wohi, wolo, NHQ * HD * HID);

    // 3) merged QKV projection
    gemm_split<<<dim3(NQKV / GBN, ROWS / GBM), 256, 65536>>>(
        xhi, xlo, wqkvhi, wqkvlo, qkvraw, ROWS, NQKV, HID);

    // 4) RMSNorm + RoPE + split
    normrope_kernel<<<dim3(NHQ + 2 * NKV, ROWS), HD>>>(
        qkvraw, qw, kw, pos, qhi, qlo, khi, klo, vhi, vlo);

    // 5) flash attention (16 warps, P-exchange) -> ctx hi/lo
    flash_kernel<<<dim3(SEQ / 128, BATCH * NHQ), 512, 230400>>>(
        qhi, qlo, khi, klo, vhi, vlo, chi, clo);

    // 6) out = ctx @ Wo
    gemm_split<<<dim3(HID / GBN, ROWS / GBM), 256, 65536>>>(
        chi, clo, wohi, wolo, out, ROWS, HID, NHQ * HD);
}

// round 14
// speedup vs baseline: 3.2150x; 3.2150x over previous
#include <cuda_runtime.h>
#include <cuda_bf16.h>
#include <math.h>

#define NHQ   16
#define NKV   8
#define HD    128
#define HID   1024
#define SEQ   2048
#define BATCH 2
#define ROWS  (BATCH*SEQ)   // 4096
#define NQKV  4096
#define EPSV  1e-6f

typedef __nv_bfloat16 bf16;

#define QSCALE 0.12753123810100868f
#define SMAX 18.0f

// ---------------- static scratch ----------------
__device__ __align__(256) float g_qkvraw[(size_t)ROWS * NQKV];
__device__ __align__(256) float2 g_rope[(size_t)SEQ * 64];

__device__ __align__(256) bf16 g_xhi[(size_t)ROWS * HID];
__device__ __align__(256) bf16 g_xlo[(size_t)ROWS * HID];
__device__ __align__(256) bf16 g_wqkvhi[(size_t)HID * NQKV];
__device__ __align__(256) bf16 g_wqkvlo[(size_t)HID * NQKV];
__device__ __align__(256) bf16 g_wohi[(size_t)NHQ * HD * HID];
__device__ __align__(256) bf16 g_wolo[(size_t)NHQ * HD * HID];

__device__ __align__(256) bf16 g_qhi[(size_t)BATCH * NHQ * SEQ * HD];
__device__ __align__(256) bf16 g_qlo[(size_t)BATCH * NHQ * SEQ * HD];
__device__ __align__(256) bf16 g_khi[(size_t)BATCH * NKV * SEQ * HD];
__device__ __align__(256) bf16 g_klo[(size_t)BATCH * NKV * SEQ * HD];
__device__ __align__(256) bf16 g_vhi[(size_t)BATCH * NKV * SEQ * HD];
__device__ __align__(256) bf16 g_vlo[(size_t)BATCH * NKV * SEQ * HD];

__device__ __align__(256) bf16 g_chi[(size_t)ROWS * NHQ * HD];
__device__ __align__(256) bf16 g_clo[(size_t)ROWS * NHQ * HD];

// ---------------- PTX helpers ----------------
__device__ __forceinline__ unsigned su32(const void* p) {
    return (unsigned)__cvta_generic_to_shared(p);
}
__device__ __forceinline__ void cp16(unsigned d, const void* s) {
    asm volatile("cp.async.ca.shared.global [%0],[%1],16;\n" :: "r"(d), "l"(s));
}
__device__ __forceinline__ void cpcommit() { asm volatile("cp.async.commit_group;\n"); }
#define CP_WAIT1() asm volatile("cp.async.wait_group 1;\n")
#define CP_WAIT0() asm volatile("cp.async.wait_group 0;\n")

__device__ __forceinline__ void ldmx4(unsigned a, unsigned& r0, unsigned& r1,
                                      unsigned& r2, unsigned& r3) {
    asm volatile("ldmatrix.sync.aligned.m8n8.x4.shared.b16 {%0,%1,%2,%3},[%4];\n"
                 : "=r"(r0), "=r"(r1), "=r"(r2), "=r"(r3) : "r"(a));
}
__device__ __forceinline__ void ldmx4t(unsigned a, unsigned& r0, unsigned& r1,
                                       unsigned& r2, unsigned& r3) {
    asm volatile("ldmatrix.sync.aligned.m8n8.x4.trans.shared.b16 {%0,%1,%2,%3},[%4];\n"
                 : "=r"(r0), "=r"(r1), "=r"(r2), "=r"(r3) : "r"(a));
}
__device__ __forceinline__ void mma16816(float* d, const unsigned* a, const unsigned* b) {
    asm volatile(
        "mma.sync.aligned.m16n8k16.row.col.f32.bf16.bf16.f32 "
        "{%0,%1,%2,%3},{%4,%5,%6,%7},{%8,%9},{%0,%1,%2,%3};\n"
        : "+f"(d[0]), "+f"(d[1]), "+f"(d[2]), "+f"(d[3])
        : "r"(a[0]), "r"(a[1]), "r"(a[2]), "r"(a[3]), "r"(b[0]), "r"(b[1]));
}
__device__ __forceinline__ float ex2(float x) {
    float r;
    asm("ex2.approx.ftz.f32 %0, %1;" : "=f"(r) : "f"(x));
    return r;
}
__device__ __forceinline__ void split2(float x, float y, unsigned& hi, unsigned& lo) {
    __nv_bfloat162 h = __floats2bfloat162_rn(x, y);
    float2 hf = __bfloat1622float2(h);
    __nv_bfloat162 l = __floats2bfloat162_rn(x - hf.x, y - hf.y);
    hi = *(unsigned*)&h;
    lo = *(unsigned*)&l;
}

// swizzled smem offsets (bytes)
__device__ __forceinline__ int offA64(int r, int k) {
    return r * 64 + ((((k >> 3) ^ ((r >> 1) & 3))) << 4) + ((k & 7) << 1);
}
__device__ __forceinline__ int off256(int r, int n) {
    return r * 256 + ((((n >> 3) ^ (r & 7))) << 4) + ((n & 7) << 1);
}

// ---------------- rope table: 2048 x 64 unique (s, j) values, computed ONCE in DP ----------------
__global__ void rope_table_kernel(const int* __restrict__ pos, float2* __restrict__ tab)
{
    int s = blockIdx.x, j = threadIdx.x;   // 2048 blocks x 64 threads
    double invf = exp(-(2.0 * j / (double)HD) * log(1.0e6));
    double ang  = (double)pos[s] * invf;
    tab[s * 64 + j] = make_float2((float)cos(ang), (float)sin(ang));
}

// ---------------- ALL input splits in one kernel ----------------
__global__ __launch_bounds__(256) void prep_all(
    const float* __restrict__ X,
    const float* __restrict__ Wq, const float* __restrict__ Wk,
    const float* __restrict__ Wv, const float* __restrict__ Wo,
    bf16* __restrict__ xhi, bf16* __restrict__ xlo,
    bf16* __restrict__ whi, bf16* __restrict__ wlo,
    bf16* __restrict__ wohi, bf16* __restrict__ wolo)
{
    const int NX = ROWS * HID;          // 4M
    const int NW = HID * NQKV;          // 4M
    const int NO = NHQ * HD * HID;      // 2M
    int total = NX + NW + NO;
    for (int i = blockIdx.x * 256 + threadIdx.x; i < total; i += gridDim.x * 256) {
        float v; bf16 *ph, *pl; int idx;
        if (i < NX) {
            v = X[i]; ph = xhi; pl = xlo; idx = i;
        } else if (i < NX + NW) {
            int j = i - NX;
            int k = j >> 12, n = j & 4095;
            if (n < 2048)      v = Wq[(size_t)k * 2048 + n];
            else if (n < 3072) v = Wk[(size_t)k * 1024 + (n - 2048)];
            else               v = Wv[(size_t)k * 1024 + (n - 3072)];
            ph = whi; pl = wlo; idx = j;
        } else {
            int j = i - NX - NW;
            v = Wo[j]; ph = wohi; pl = wolo; idx = j;
        }
        bf16 h = __float2bfloat16(v);
        ph[idx] = h;
        pl[idx] = __float2bfloat16(v - __bfloat162float(h));
    }
}

// ================= double-buffered bf16-split GEMM (NN) =================
constexpr int GBM = 128, GBN = 128, GBK = 32;

__global__ __launch_bounds__(256) void gemm_split(
    const bf16* __restrict__ Ahi, const bf16* __restrict__ Alo,
    const bf16* __restrict__ Bhi, const bf16* __restrict__ Blo,
    float* __restrict__ C, int M, int N, int K)
{
    extern __shared__ char sm[];
    int tid = threadIdx.x, lane = tid & 31, warp = tid >> 5;
    int bx = blockIdx.x, by = blockIdx.y;
    int wm = warp >> 2, wn = warp & 3;

    float acc[4][4][4];
    #pragma unroll
    for (int a = 0; a < 4; a++)
        #pragma unroll
        for (int b = 0; b < 4; b++)
            #pragma unroll
            for (int c = 0; c < 4; c++) acc[a][b][c] = 0.f;

    int nIter = K / GBK;

    int ar = tid >> 2, ag = (tid & 3) << 3;
    int bkr = tid >> 4, bg = (tid & 15) << 3;

    auto issue = [&](int st, int k0) {
        char* base = sm + st * 32768;
        #pragma unroll
        for (int p = 0; p < 2; p++) {
            int r = ar + p * 64;
            int so = offA64(r, ag);
            size_t go = (size_t)(by * GBM + r) * K + k0 + ag;
            cp16(su32(base + so), Ahi + go);
            cp16(su32(base + 8192 + so), Alo + go);
        }
        #pragma unroll
        for (int p = 0; p < 2; p++) {
            int kr = bkr + p * 16;
            int so = off256(kr, bg);
            size_t go = (size_t)(k0 + kr) * N + bx * GBN + bg;
            cp16(su32(base + 16384 + so), Bhi + go);
            cp16(su32(base + 24576 + so), Blo + go);
        }
    };

    issue(0, 0);
    cpcommit();

    int arow = (lane & 7) + ((lane >> 3) & 1) * 8;
    int aksel = (lane >> 4) * 8;
    int tk = (lane & 7) + ((lane >> 3) & 1) * 8;
    int tn = (lane >> 4) * 8;

    for (int it = 0; it < nIter; ++it) {
        if (it + 1 < nIter) {
            issue((it + 1) & 1, (it + 1) * GBK);
            cpcommit();
            CP_WAIT1();
        } else {
            CP_WAIT0();
        }
        __syncthreads();
        char* base = sm + (it & 1) * 32768;

        #pragma unroll
        for (int ks = 0; ks < GBK; ks += 16) {
            unsigned ah[4][4], al[4][4], bh[4][2], bl[4][2];
            #pragma unroll
            for (int mt = 0; mt < 4; mt++) {
                int so = offA64(wm * 64 + mt * 16 + arow, ks + aksel);
                ldmx4(su32(base + so), ah[mt][0], ah[mt][1], ah[mt][2], ah[mt][3]);
                ldmx4(su32(base + 8192 + so), al[mt][0], al[mt][1], al[mt][2], al[mt][3]);
            }
            #pragma unroll
            for (int ng = 0; ng < 2; ng++) {
                int so = off256(ks + tk, wn * 32 + ng * 16 + tn);
                unsigned r0, r1, r2, r3;
                ldmx4t(su32(base + 16384 + so), r0, r1, r2, r3);
                bh[2 * ng][0] = r0; bh[2 * ng][1] = r1;
                bh[2 * ng + 1][0] = r2; bh[2 * ng + 1][1] = r3;
                ldmx4t(su32(base + 24576 + so), r0, r1, r2, r3);
                bl[2 * ng][0] = r0; bl[2 * ng][1] = r1;
                bl[2 * ng + 1][0] = r2; bl[2 * ng + 1][1] = r3;
            }
            #pragma unroll
            for (int mt = 0; mt < 4; mt++)
                #pragma unroll
                for (int nf = 0; nf < 4; nf++) {
                    mma16816(acc[mt][nf], ah[mt], bh[nf]);
                    mma16816(acc[mt][nf], ah[mt], bl[nf]);
                    mma16816(acc[mt][nf], al[mt], bh[nf]);
                }
        }
        __syncthreads();
    }

    #pragma unroll
    for (int mt = 0; mt < 4; mt++)
        #pragma unroll
        for (int nf = 0; nf < 4; nf++) {
            int r = by * GBM + wm * 64 + mt * 16 + (lane >> 2);
            int c = bx * GBN + wn * 32 + nf * 8 + (lane & 3) * 2;
            *(float2*)(C + (size_t)r * N + c) = make_float2(acc[mt][nf][0], acc[mt][nf][1]);
            *(float2*)(C + (size_t)(r + 8) * N + c) = make_float2(acc[mt][nf][2], acc[mt][nf][3]);
        }
}

// ================= fused flash attention (R9 best config: 256 thr, static-max) =================
__global__ __launch_bounds__(256) void flash_kernel(
    const bf16* __restrict__ qhi, const bf16* __restrict__ qlo,
    const bf16* __restrict__ khi, const bf16* __restrict__ klo,
    const bf16* __restrict__ vhi, const bf16* __restrict__ vlo,
    bf16* __restrict__ chi, bf16* __restrict__ clo)
{
    extern __shared__ char sm[];
    int tid = threadIdx.x, lane = tid & 31, wid = tid >> 5;
    int qt = (gridDim.x - 1) - blockIdx.x;
    int bh = blockIdx.y;
    int b = bh >> 4, h = bh & 15, kvh = h >> 1;

    size_t qbase = ((size_t)(b * NHQ + h) * SEQ + (size_t)qt * 128) * HD;
    size_t kvbase = (size_t)(b * NKV + kvh) * SEQ * HD;

    #pragma unroll
    for (int p = 0; p < 8; p++) {
        int idx = tid + p * 256;
        int r = idx >> 4, g = (idx & 15) << 3;
        int so = off256(r, g);
        size_t go = qbase + (size_t)r * HD + g;
        cp16(su32(sm + so), qhi + go);
        cp16(su32(sm + 32768 + so), qlo + go);
    }
    cpcommit();

    auto issueKV = [&](int st, int kt) {
        char* base = sm + 65536 + st * 65536;
        size_t kb = kvbase + (size_t)kt * 64 * HD;
        #pragma unroll
        for (int p = 0; p < 4; p++) {
            int idx = tid + p * 256;
            int r = idx >> 4, g = (idx & 15) << 3;
            int so = off256(r, g);
            size_t go = kb + (size_t)r * HD + g;
            cp16(su32(base + so), khi + go);
            cp16(su32(base + 16384 + so), klo + go);
            cp16(su32(base + 32768 + so), vhi + go);
            cp16(su32(base + 49152 + so), vlo + go);
        }
    };

    int nT = 2 * qt + 2;
    issueKV(0, 0);
    cpcommit();

    float oacc[16][4];
    #pragma unroll
    for (int f = 0; f < 16; f++)
        #pragma unroll
        for (int c = 0; c < 4; c++) oacc[f][c] = 0.f;
    float l0 = 0.f, l1 = 0.f;

    int arow = (lane & 7) + ((lane >> 3) & 1) * 8;
    int aksel = (lane >> 4) * 8;
    int bn = (lane & 7) + (lane >> 4) * 8;
    int bk = ((lane >> 3) & 1) * 8;
    int tk = (lane & 7) + ((lane >> 3) & 1) * 8;
    int tn = (lane >> 4) * 8;
    int r0g = qt * 128 + wid * 16 + (lane >> 2);

    for (int kt = 0; kt < nT; ++kt) {
        if (kt + 1 < nT) {
            issueKV((kt + 1) & 1, kt + 1);
            cpcommit();
            CP_WAIT1();
        } else {
            CP_WAIT0();
        }
        __syncthreads();
        char* kbase = sm + 65536 + (kt & 1) * 65536;
        char* vbase = kbase + 32768;

        float sacc[8][4];
        #pragma unroll
        for (int f = 0; f < 8; f++)
            #pragma unroll
            for (int c = 0; c < 4; c++) sacc[f][c] = -SMAX;

        #pragma unroll
        for (int ks = 0; ks < HD; ks += 16) {
            unsigned qh[4], ql[4];
            int qo = off256(wid * 16 + arow, ks + aksel);
            ldmx4(su32(sm + qo), qh[0], qh[1], qh[2], qh[3]);
            ldmx4(su32(sm + 32768 + qo), ql[0], ql[1], ql[2], ql[3]);
            #pragma unroll
            for (int ng = 0; ng < 4; ng++) {
                int so = off256(ng * 16 + bn, ks + bk);
                unsigned r0, r1, r2, r3;
                unsigned kh0[2], kh1[2], kl0[2], kl1[2];
                ldmx4(su32(kbase + so), r0, r1, r2, r3);
                kh0[0] = r0; kh0[1] = r1; kh1[0] = r2; kh1[1] = r3;
                ldmx4(su32(kbase + 16384 + so), r0, r1, r2, r3);
                kl0[0] = r0; kl0[1] = r1; kl1[0] = r2; kl1[1] = r3;
                mma16816(sacc[2 * ng], qh, kh0);
                mma16816(sacc[2 * ng], qh, kl0);
                mma16816(sacc[2 * ng], ql, kh0);
                mma16816(sacc[2 * ng + 1], qh, kh1);
                mma16816(sacc[2 * ng + 1], qh, kl1);
                mma16816(sacc[2 * ng + 1], ql, kh1);
            }
        }

        if (kt >= 2 * qt) {
            #pragma unroll
            for (int nf = 0; nf < 8; nf++) {
                int col = kt * 64 + nf * 8 + (lane & 3) * 2;
                if (col > r0g)     sacc[nf][0] = -10000.f;
                if (col + 1 > r0g) sacc[nf][1] = -10000.f;
                if (col > r0g + 8)     sacc[nf][2] = -10000.f;
                if (col + 1 > r0g + 8) sacc[nf][3] = -10000.f;
            }
        }

        float ps0 = 0.f, ps1 = 0.f;
        #pragma unroll
        for (int nf = 0; nf < 8; nf++) {
            sacc[nf][0] = ex2(sacc[nf][0]);
            sacc[nf][1] = ex2(sacc[nf][1]);
            sacc[nf][2] = ex2(sacc[nf][2]);
            sacc[nf][3] = ex2(sacc[nf][3]);
            ps0 += sacc[nf][0] + sacc[nf][1];
            ps1 += sacc[nf][2] + sacc[nf][3];
        }
        l0 += ps0;
        l1 += ps1;

        unsigned pah[4][4], pal[4][4];
        #pragma unroll
        for (int j = 0; j < 4; j++) {
            split2(sacc[2 * j][0], sacc[2 * j][1], pah[j][0], pal[j][0]);
            split2(sacc[2 * j][2], sacc[2 * j][3], pah[j][1], pal[j][1]);
            split2(sacc[2 * j + 1][0], sacc[2 * j + 1][1], pah[j][2], pal[j][2]);
            split2(sacc[2 * j + 1][2], sacc[2 * j + 1][3], pah[j][3], pal[j][3]);
        }

        #pragma unroll
        for (int j = 0; j < 4; j++) {
            #pragma unroll
            for (int ng2 = 0; ng2 < 8; ng2++) {
                int so = off256(j * 16 + tk, ng2 * 16 + tn);
                unsigned r0, r1, r2, r3, s0, s1, s2, s3;
                ldmx4t(su32(vbase + so), r0, r1, r2, r3);
                ldmx4t(su32(vbase + 16384 + so), s0, s1, s2, s3);
                unsigned vh0[2] = {r0, r1}, vh1[2] = {r2, r3};
                unsigned vl0[2] = {s0, s1}, vl1[2] = {s2, s3};
                mma16816(oacc[2 * ng2], pah[j], vh0);
                mma16816(oacc[2 * ng2], pal[j], vh0);
                mma16816(oacc[2 * ng2], pah[j], vl0);
                mma16816(oacc[2 * ng2 + 1], pah[j], vh1);
                mma16816(oacc[2 * ng2 + 1], pal[j], vh1);
                mma16816(oacc[2 * ng2 + 1], pah[j], vl1);
            }
        }
        __syncthreads();
    }

    l0 += __shfl_xor_sync(0xffffffffu, l0, 1);
    l0 += __shfl_xor_sync(0xffffffffu, l0, 2);
    l1 += __shfl_xor_sync(0xffffffffu, l1, 1);
    l1 += __shfl_xor_sync(0xffffffffu, l1, 2);
    float i0 = 1.f / l0, i1 = 1.f / l1;

    size_t row0 = (size_t)b * SEQ + qt * 128 + wid * 16 + (lane >> 2);
    #pragma unroll
    for (int nf = 0; nf < 16; nf++) {
        int col = h * HD + nf * 8 + (lane & 3) * 2;
        unsigned hi, lo;
        split2(oacc[nf][0] * i0, oacc[nf][1] * i0, hi, lo);
        *(unsigned*)(chi + row0 * (NHQ * HD) + col) = hi;
        *(unsigned*)(clo + row0 * (NHQ * HD) + col) = lo;
        split2(oacc[nf][2] * i1, oacc[nf][3] * i1, hi, lo);
        *(unsigned*)(chi + (row0 + 8) * (NHQ * HD) + col) = hi;
        *(unsigned*)(clo + (row0 + 8) * (NHQ * HD) + col) = lo;
    }
}

// ---------------- RMSNorm + RoPE (table-based) + split ----------------
__device__ __forceinline__ float blockSum128(float v) {
    #pragma unroll
    for (int o = 16; o > 0; o >>= 1) v += __shfl_xor_sync(0xffffffffu, v, o);
    __shared__ float s[4];
    if ((threadIdx.x & 31) == 0) s[threadIdx.x >> 5] = v;
    __syncthreads();
    float r = s[0] + s[1] + s[2] + s[3];
    __syncthreads();
    return r;
}

__global__ __launch_bounds__(HD) void normrope_kernel(
    const float* __restrict__ qkvraw,
    const float* __restrict__ qw, const float* __restrict__ kw,
    const float2* __restrict__ rope,
    bf16* __restrict__ qhi, bf16* __restrict__ qlo,
    bf16* __restrict__ khi, bf16* __restrict__ klo,
    bf16* __restrict__ vhi, bf16* __restrict__ vlo)
{
    int row = blockIdx.y;
    int hh  = blockIdx.x;
    int t   = threadIdx.x;
    int b   = row / SEQ, s = row - b * SEQ;

    if (hh >= NHQ + NKV) {
        int kvh = hh - NHQ - NKV;
        float x = qkvraw[(size_t)row * NQKV + 3072 + kvh * HD + t];
        size_t o = (((size_t)(b * NKV + kvh)) * SEQ + s) * HD + t;
        bf16 hv = __float2bfloat16(x);
        vhi[o] = hv;
        vlo[o] = __float2bfloat16(x - __bfloat162float(hv));
        return;
    }

    float x; const float* w;
    bf16 *dhi, *dlo;
    bool isq = (hh < NHQ);
    if (isq) {
        x = qkvraw[(size_t)row * NQKV + hh * HD + t];
        w = qw;
        size_t o = (((size_t)(b * NHQ + hh)) * SEQ + s) * HD + t;
        dhi = qhi + o; dlo = qlo + o;
    } else {
        int kvh = hh - NHQ;
        x = qkvraw[(size_t)row * NQKV + 2048 + kvh * HD + t];
        w = kw;
        size_t o = (((size_t)(b * NKV + kvh)) * SEQ + s) * HD + t;
        dhi = khi + o; dlo = klo + o;
    }

    float ms = blockSum128(x * x) * (1.0f / HD);
    float nv = w[t] * (x * rsqrtf(ms + EPSV));

    __shared__ float sh[HD];
    sh[t] = nv;
    __syncthreads();

    float2 cs = rope[s * 64 + (t & 63)];
    float partner = (t < 64) ? -sh[t + 64] : sh[t - 64];
    float val = nv * cs.x + partner * cs.y;
    if (isq) val *= QSCALE;

    bf16 hv = __float2bfloat16(val);
    *dhi = hv;
    *dlo = __float2bfloat16(val - __bfloat162float(hv));
}

// ---------------- launch ----------------
template <typename T>
static T* symaddr(const void* sym) {
    void* p = nullptr;
    cudaGetSymbolAddress(&p, sym);
    return (T*)p;
}

extern "C" void kernel_launch(void* const* d_in, const int* in_sizes, int n_in,
                              void* d_out, int out_size)
{
    const float* X   = (const float*)d_in[0];
    const int*   pos = (const int*)d_in[1];
    const float* Wq  = (const float*)d_in[2];
    const float* Wk  = (const float*)d_in[3];
    const float* Wv  = (const float*)d_in[4];
    const float* Wo  = (const float*)d_in[5];
    const float* qw  = (const float*)d_in[6];
    const float* kw  = (const float*)d_in[7];
    float* out = (float*)d_out;

    float* qkvraw = symaddr<float>(g_qkvraw);
    float2* rope  = symaddr<float2>(g_rope);
    bf16* xhi = symaddr<bf16>(g_xhi);       bf16* xlo = symaddr<bf16>(g_xlo);
    bf16* wqkvhi = symaddr<bf16>(g_wqkvhi); bf16* wqkvlo = symaddr<bf16>(g_wqkvlo);
    bf16* wohi = symaddr<bf16>(g_wohi);     bf16* wolo = symaddr<bf16>(g_wolo);
    bf16* qhi = symaddr<bf16>(g_qhi);       bf16* qlo = symaddr<bf16>(g_qlo);
    bf16* khi = symaddr<bf16>(g_khi);       bf16* klo = symaddr<bf16>(g_klo);
    bf16* vhi = symaddr<bf16>(g_vhi);       bf16* vlo = symaddr<bf16>(g_vlo);
    bf16* chi = symaddr<bf16>(g_chi);       bf16* clo = symaddr<bf16>(g_clo);

    static int attr_done = 0;
    if (!attr_done) {
        cudaFuncSetAttribute(gemm_split, cudaFuncAttributeMaxDynamicSharedMemorySize, 65536);
        cudaFuncSetAttribute(flash_kernel, cudaFuncAttributeMaxDynamicSharedMemorySize, 196608);
        attr_done = 1;
    }

    // 0) rope table (131K DP computations instead of 12.6M)
    rope_table_kernel<<<SEQ, 64>>>(pos, rope);
    // 1) all input splits in one launch
    prep_all<<<2048, 256>>>(X, Wq, Wk, Wv, Wo, xhi, xlo, wqkvhi, wqkvlo, wohi, wolo);
    // 2) merged QKV projection
    gemm_split<<<dim3(NQKV / GBN, ROWS / GBM), 256, 65536>>>(
        xhi, xlo, wqkvhi, wqkvlo, qkvraw, ROWS, NQKV, HID);
    // 3) RMSNorm + RoPE (table) + split   <-- PROFILED SLOT
    normrope_kernel<<<dim3(NHQ + 2 * NKV, ROWS), HD>>>(
        qkvraw, qw, kw, rope, qhi, qlo, khi, klo, vhi, vlo);
    // 4) flash attention -> ctx hi/lo
    flash_kernel<<<dim3(SEQ / 128, BATCH * NHQ), 256, 196608>>>(
        qhi, qlo, khi, klo, vhi, vlo, chi, clo);
    // 5) out = ctx @ Wo
    gemm_split<<<dim3(HID / GBN, ROWS / GBM), 256, 65536>>>(
        chi, clo, wohi, wolo, out, ROWS, HID, NHQ * HD);
}